// round 3
// baseline (speedup 1.0000x reference)
#include <cuda_runtime.h>
#include <mma.h>
#include <math.h>

using namespace nvcuda;

#define D 128
#define NHEADS 8
#define NMAX 50000

// ---- scratch (no allocations allowed; device globals) ----
__device__ float g_Q[NMAX * D];
__device__ float g_K[NMAX * D];
__device__ float g_V[NMAX * D];
__device__ float g_wV[NMAX * D];
__device__ float g_z[NMAX * NHEADS];
__device__ float g_h[NMAX * D];
__device__ float g_g[NMAX * D];

__device__ __forceinline__ float tf32_hi(float x) {
    unsigned r;
    asm("cvt.rna.tf32.f32 %0, %1;" : "=r"(r) : "f"(x));
    return __uint_as_float(r);
}

// ============================================================
// wmma tf32x3 GEMM: C[M,128] = A[M,128] @ W[128,128] + bias
// MODE 0: plain.  MODE 1: C = R + relu(A@W + bias)
// Block: 128x128 C tile, 256 threads = 8 warps in 2(m) x 4(n).
// Each warp: 64x32 = 4x2 wmma m16n16k8 frags.
// Static smem only (< 48KB): BK=16 hi/lo tiles + epilogue staging.
// ============================================================
#define BK 16
#define AS_LD 20    // 16 + 4 pad, 80B: multiple of 16B
#define BS_LD 132   // 128 + 4 pad, 528B: multiple of 16B
#define ST_LD 20    // staging ld, 80B: multiple of 16B

template <int MODE>
__device__ __forceinline__ void gemm_tc(
    const float* __restrict__ A, const float* __restrict__ W,
    const float* __restrict__ bias, float* __restrict__ C,
    const float* __restrict__ R, int M)
{
    __shared__ float As_hi[128 * AS_LD];   // 2560 f
    __shared__ float As_lo[128 * AS_LD];   // 2560 f
    __shared__ float Bs_hi[BK * BS_LD];    // 2112 f
    __shared__ float Bs_lo[BK * BS_LD];    // 2112 f
    __shared__ float stage[8][16 * ST_LD]; // 2560 f    total 11904 f = 47616 B

    const int tid    = threadIdx.x;
    const int warp   = tid >> 5;
    const int lane   = tid & 31;
    const int warp_m = warp & 1;     // 0..1 -> 64-row half
    const int warp_n = warp >> 1;    // 0..3 -> 32-col quarter
    const int row0   = blockIdx.x * 128;

    wmma::fragment<wmma::accumulator, 16, 16, 8, float> c[4][2];
#pragma unroll
    for (int im = 0; im < 4; im++)
#pragma unroll
        for (int jn = 0; jn < 2; jn++) wmma::fill_fragment(c[im][jn], 0.0f);

    const int arow = tid >> 1;           // 0..127
    const int acol = (tid & 1) * 8;      // 0 or 8
    const int brow = tid >> 4;           // 0..15
    const int bcol = (tid & 15) * 8;     // 0..120

    for (int kk = 0; kk < 128; kk += BK) {
        __syncthreads();
        // ---- load & split A chunk [128 x 16] ----
        {
            int r = row0 + arow;
            const float* srcp = A + (size_t)r * 128 + kk + acol;
            float* dh = As_hi + arow * AS_LD + acol;
            float* dl = As_lo + arow * AS_LD + acol;
#pragma unroll
            for (int i = 0; i < 8; i += 4) {
                float4 v = (r < M) ? *(const float4*)(srcp + i)
                                   : make_float4(0.f, 0.f, 0.f, 0.f);
                float vv[4] = {v.x, v.y, v.z, v.w};
#pragma unroll
                for (int u = 0; u < 4; u++) {
                    float hi = tf32_hi(vv[u]);
                    dh[i + u] = hi;
                    dl[i + u] = tf32_hi(vv[u] - hi);
                }
            }
        }
        // ---- load & split W chunk [16 x 128] ----
        {
            const float* srcp = W + (size_t)(kk + brow) * 128 + bcol;
            float* dh = Bs_hi + brow * BS_LD + bcol;
            float* dl = Bs_lo + brow * BS_LD + bcol;
#pragma unroll
            for (int i = 0; i < 8; i += 4) {
                float4 v = *(const float4*)(srcp + i);
                float vv[4] = {v.x, v.y, v.z, v.w};
#pragma unroll
                for (int u = 0; u < 4; u++) {
                    float hi = tf32_hi(vv[u]);
                    dh[i + u] = hi;
                    dl[i + u] = tf32_hi(vv[u] - hi);
                }
            }
        }
        __syncthreads();

#pragma unroll
        for (int ks = 0; ks < 2; ks++) {
            const int k0 = ks * 8;
            wmma::fragment<wmma::matrix_b, 16, 16, 8, wmma::precision::tf32, wmma::row_major> b_hi[2], b_lo[2];
#pragma unroll
            for (int jn = 0; jn < 2; jn++) {
                const int n0 = warp_n * 32 + jn * 16;
                wmma::load_matrix_sync(b_hi[jn], Bs_hi + k0 * BS_LD + n0, BS_LD);
                wmma::load_matrix_sync(b_lo[jn], Bs_lo + k0 * BS_LD + n0, BS_LD);
            }
#pragma unroll
            for (int im = 0; im < 4; im++) {
                const int m0 = warp_m * 64 + im * 16;
                wmma::fragment<wmma::matrix_a, 16, 16, 8, wmma::precision::tf32, wmma::row_major> a_hi, a_lo;
                wmma::load_matrix_sync(a_hi, As_hi + m0 * AS_LD + k0, AS_LD);
                wmma::load_matrix_sync(a_lo, As_lo + m0 * AS_LD + k0, AS_LD);
#pragma unroll
                for (int jn = 0; jn < 2; jn++) {
                    wmma::mma_sync(c[im][jn], a_hi, b_hi[jn], c[im][jn]);
                    wmma::mma_sync(c[im][jn], a_hi, b_lo[jn], c[im][jn]);
                    wmma::mma_sync(c[im][jn], a_lo, b_hi[jn], c[im][jn]);
                }
            }
        }
    }

    // ---- epilogue via per-warp staging (known addressing) ----
    const int r  = lane >> 1;          // 0..15
    const int cc = (lane & 1) * 8;     // 0 or 8
#pragma unroll
    for (int im = 0; im < 4; im++) {
#pragma unroll
        for (int jn = 0; jn < 2; jn++) {
            wmma::store_matrix_sync(&stage[warp][0], c[im][jn], ST_LD, wmma::mem_row_major);
            __syncwarp();
            const int grow = row0 + warp_m * 64 + im * 16 + r;
            const int gcol = warp_n * 32 + jn * 16 + cc;
            if (grow < M) {
                float v[8];
#pragma unroll
                for (int u = 0; u < 8; u++) {
                    float val = stage[warp][r * ST_LD + cc + u] + bias[gcol + u];
                    if (MODE == 1)
                        val = R[(size_t)grow * 128 + gcol + u] + fmaxf(val, 0.0f);
                    v[u] = val;
                }
                *(float4*)(C + (size_t)grow * 128 + gcol)     = make_float4(v[0], v[1], v[2], v[3]);
                *(float4*)(C + (size_t)grow * 128 + gcol + 4) = make_float4(v[4], v[5], v[6], v[7]);
            }
            __syncwarp();
        }
    }
}

__global__ __launch_bounds__(256) void qkv_kernel(
    const float* __restrict__ x,
    const float* __restrict__ Wq, const float* __restrict__ bq,
    const float* __restrict__ Wk, const float* __restrict__ bk,
    const float* __restrict__ Wv, const float* __restrict__ bv, int M)
{
    if (blockIdx.y == 0)      gemm_tc<0>(x, Wq, bq, g_Q, nullptr, M);
    else if (blockIdx.y == 1) gemm_tc<0>(x, Wk, bk, g_K, nullptr, M);
    else                      gemm_tc<0>(x, Wv, bv, g_V, nullptr, M);
}

__global__ __launch_bounds__(256) void out_gemm_kernel(
    const float* __restrict__ Wo, const float* __restrict__ bo,
    float* __restrict__ out, int M)
{
    gemm_tc<1>(g_g, Wo, bo, out, g_h, M);
}

// ============================================================
// zero wV / z accumulators
// ============================================================
__global__ void zero_kernel(int n_wv, int n_z)
{
    int i = blockIdx.x * blockDim.x + threadIdx.x;
    int stride = gridDim.x * blockDim.x;
    for (int j = i; j < n_wv; j += stride) g_wV[j] = 0.0f;
    for (int j = i; j < n_z;  j += stride) g_z[j]  = 0.0f;
}

// ============================================================
// edge kernel: one warp per edge.
// ============================================================
__global__ __launch_bounds__(256) void edge_kernel(
    const int* __restrict__ src, const int* __restrict__ dst, int E)
{
    int w = (int)((blockIdx.x * blockDim.x + threadIdx.x) >> 5);
    int lane = threadIdx.x & 31;
    if (w >= E) return;
    int s = src[w];
    int d = dst[w];

    const float4* Q4 = (const float4*)g_Q;
    const float4* K4 = (const float4*)g_K;
    const float4* V4 = (const float4*)g_V;

    float4 q = Q4[(size_t)d * 32 + lane];
    float4 k = K4[(size_t)s * 32 + lane];
    float4 v = V4[(size_t)s * 32 + lane];

    float p = q.x * k.x + q.y * k.y + q.z * k.z + q.w * k.w;
    p += __shfl_xor_sync(0xffffffffu, p, 1);
    p += __shfl_xor_sync(0xffffffffu, p, 2);
    float sc = p * 0.25f;                 // 1/sqrt(16)
    sc = fminf(fmaxf(sc, -5.0f), 5.0f);
    sc = expf(sc);

    if ((lane & 3) == 0) {
        float* zp = &g_z[(size_t)d * NHEADS + (lane >> 2)];
        asm volatile("red.global.add.f32 [%0], %1;" :: "l"(zp), "f"(sc) : "memory");
    }

    float* wp = &g_wV[(size_t)d * 128 + lane * 4];
    asm volatile("red.global.add.v4.f32 [%0], {%1,%2,%3,%4};"
                 :: "l"(wp), "f"(v.x * sc), "f"(v.y * sc), "f"(v.z * sc), "f"(v.w * sc)
                 : "memory");
}

// ============================================================
// attn normalize + residual + LN1 -> h ; LN2(h) -> g
// ============================================================
__global__ __launch_bounds__(256) void attn_ln_kernel(
    const float* __restrict__ x,
    const float* __restrict__ gamma1, const float* __restrict__ beta1,
    const float* __restrict__ gamma2, const float* __restrict__ beta2, int M)
{
    int w = (int)((blockIdx.x * blockDim.x + threadIdx.x) >> 5);
    int lane = threadIdx.x & 31;
    if (w >= M) return;

    const float4* x4  = (const float4*)x;
    const float4* wv4 = (const float4*)g_wV;

    float4 xv = x4[(size_t)w * 32 + lane];
    float4 wv = wv4[(size_t)w * 32 + lane];
    float inv = 1.0f / (g_z[(size_t)w * NHEADS + (lane >> 2)] + 1e-3f);

    float4 y;
    y.x = xv.x + wv.x * inv;
    y.y = xv.y + wv.y * inv;
    y.z = xv.z + wv.z * inv;
    y.w = xv.w + wv.w * inv;

    float s  = y.x + y.y + y.z + y.w;
    float sq = y.x * y.x + y.y * y.y + y.z * y.z + y.w * y.w;
#pragma unroll
    for (int o = 16; o > 0; o >>= 1) {
        s  += __shfl_xor_sync(0xffffffffu, s, o);
        sq += __shfl_xor_sync(0xffffffffu, sq, o);
    }
    float mu   = s * (1.0f / 128.0f);
    float var  = sq * (1.0f / 128.0f) - mu * mu;
    float rstd = rsqrtf(var + 1e-5f);

    float4 g1 = ((const float4*)gamma1)[lane];
    float4 b1 = ((const float4*)beta1)[lane];
    float4 hv;
    hv.x = (y.x - mu) * rstd * g1.x + b1.x;
    hv.y = (y.y - mu) * rstd * g1.y + b1.y;
    hv.z = (y.z - mu) * rstd * g1.z + b1.z;
    hv.w = (y.w - mu) * rstd * g1.w + b1.w;
    ((float4*)g_h)[(size_t)w * 32 + lane] = hv;

    float s2  = hv.x + hv.y + hv.z + hv.w;
    float sq2 = hv.x * hv.x + hv.y * hv.y + hv.z * hv.z + hv.w * hv.w;
#pragma unroll
    for (int o = 16; o > 0; o >>= 1) {
        s2  += __shfl_xor_sync(0xffffffffu, s2, o);
        sq2 += __shfl_xor_sync(0xffffffffu, sq2, o);
    }
    float mu2   = s2 * (1.0f / 128.0f);
    float var2  = sq2 * (1.0f / 128.0f) - mu2 * mu2;
    float rstd2 = rsqrtf(var2 + 1e-5f);

    float4 g2 = ((const float4*)gamma2)[lane];
    float4 b2 = ((const float4*)beta2)[lane];
    float4 gv;
    gv.x = (hv.x - mu2) * rstd2 * g2.x + b2.x;
    gv.y = (hv.y - mu2) * rstd2 * g2.y + b2.y;
    gv.z = (hv.z - mu2) * rstd2 * g2.z + b2.z;
    gv.w = (hv.w - mu2) * rstd2 * g2.w + b2.w;
    ((float4*)g_g)[(size_t)w * 32 + lane] = gv;
}

// ============================================================
extern "C" void kernel_launch(void* const* d_in, const int* in_sizes, int n_in,
                              void* d_out, int out_size)
{
    const float* x      = (const float*)d_in[0];
    const int*   src    = (const int*)  d_in[1];
    const int*   dst    = (const int*)  d_in[2];
    const float* Wq     = (const float*)d_in[3];
    const float* bq     = (const float*)d_in[4];
    const float* Wk     = (const float*)d_in[5];
    const float* bk     = (const float*)d_in[6];
    const float* Wv     = (const float*)d_in[7];
    const float* bv     = (const float*)d_in[8];
    const float* Wo     = (const float*)d_in[9];
    const float* bo     = (const float*)d_in[10];
    const float* gamma1 = (const float*)d_in[11];
    const float* beta1  = (const float*)d_in[12];
    const float* gamma2 = (const float*)d_in[13];
    const float* beta2  = (const float*)d_in[14];
    float* out = (float*)d_out;

    int M = in_sizes[0] / 128;
    int E = in_sizes[1];

    zero_kernel<<<512, 256>>>(M * 128, M * NHEADS);

    dim3 gq((M + 127) / 128, 3);
    qkv_kernel<<<gq, 256>>>(x, Wq, bq, Wk, bk, Wv, bv, M);

    int edge_blocks = (E + 7) / 8;  // 8 warps/block
    edge_kernel<<<edge_blocks, 256>>>(src, dst, E);

    attn_ln_kernel<<<(M * 32 + 255) / 256, 256>>>(x, gamma1, beta1, gamma2, beta2, M);

    out_gemm_kernel<<<(M + 127) / 128, 256>>>(Wo, bo, out, M);
}

// round 5
// speedup vs baseline: 1.4556x; 1.4556x over previous
#include <cuda_runtime.h>
#include <math.h>
#include <stdint.h>

#define D 128
#define NHEADS 8
#define NMAX 50000

// ---- scratch (no allocations allowed; device globals) ----
__device__ float g_Q[NMAX * D];
__device__ float g_K[NMAX * D];
__device__ float g_V[NMAX * D];
__device__ float g_wV[NMAX * D];
__device__ float g_z[NMAX * NHEADS];
__device__ float g_h[NMAX * D];
__device__ float g_g[NMAX * D];

// ---- packed f32x2 helpers (Blackwell FFMA2 path) ----
__device__ __forceinline__ unsigned long long pack_dup(float a) {
    unsigned long long r;
    asm("mov.b64 %0, {%1, %1};" : "=l"(r) : "f"(a));
    return r;
}
__device__ __forceinline__ void fma2(unsigned long long& acc,
                                     unsigned long long a,
                                     unsigned long long b) {
    asm("fma.rn.f32x2 %0, %1, %2, %0;" : "+l"(acc) : "l"(a), "l"(b));
}
__device__ __forceinline__ void unpack2(float& lo, float& hi, unsigned long long v) {
    asm("mov.b64 {%0, %1}, %2;" : "=f"(lo), "=f"(hi) : "l"(v));
}

// ============================================================
// SGEMM via packed FFMA2: C[M,128] = A[M,128] @ W[128,128] + bias
// MODE 0: plain.  MODE 1: C = R + relu(A@W + bias)
// BM=BN=128, BK=32, 256 threads, 8x8 microtile per thread,
// accumulators held as 8x4 f32x2 pairs along n.
// ============================================================
template <int MODE>
__device__ __forceinline__ void gemm_body(
    const float* __restrict__ A, const float* __restrict__ W,
    const float* __restrict__ bias, float* __restrict__ C,
    const float* __restrict__ R, int M)
{
    __shared__ float As[32][129];   // [k][m], pad 129 -> conflict-free transposed stores
    __shared__ float Bs[32][128];   // [k][n]

    const int tid  = threadIdx.x;          // 0..255
    const int tx   = tid & 15;             // 0..15 -> n
    const int ty   = tid >> 4;             // 0..15 -> m
    const int row0 = blockIdx.x * 128;

    unsigned long long acc[8][4];
#pragma unroll
    for (int i = 0; i < 8; i++)
#pragma unroll
        for (int j = 0; j < 4; j++) acc[i][j] = 0ULL;

    const int arow = tid >> 3;            // 0..31
    const int acol = (tid & 7) << 2;      // 0,4,...,28
    const int brow = tid >> 5;            // 0..7
    const int bcol = (tid & 31) << 2;     // 0..124

    for (int kk = 0; kk < 128; kk += 32) {
        __syncthreads();
        // A tile (transposed into As[k][m])
#pragma unroll
        for (int p = 0; p < 4; p++) {
            int r = row0 + arow + p * 32;
            float4 v = make_float4(0.f, 0.f, 0.f, 0.f);
            if (r < M) v = *(const float4*)(A + (size_t)r * 128 + kk + acol);
            int m = arow + p * 32;
            As[acol + 0][m] = v.x;
            As[acol + 1][m] = v.y;
            As[acol + 2][m] = v.z;
            As[acol + 3][m] = v.w;
        }
        // W tile
#pragma unroll
        for (int p = 0; p < 4; p++) {
            int r = kk + brow + p * 8;
            *(float4*)&Bs[brow + p * 8][bcol] =
                *(const float4*)(W + (size_t)r * 128 + bcol);
        }
        __syncthreads();

#pragma unroll
        for (int k = 0; k < 32; k++) {
            unsigned long long ap[8];
#pragma unroll
            for (int i = 0; i < 8; i++) ap[i] = pack_dup(As[k][ty * 8 + i]);
            // b pairs: 16B-aligned, 2x LDS.128 worth
            const ulonglong2* bp = (const ulonglong2*)&Bs[k][tx * 8];
            ulonglong2 bq0 = bp[0];
            ulonglong2 bq1 = bp[1];
            unsigned long long b2[4] = {bq0.x, bq0.y, bq1.x, bq1.y};
#pragma unroll
            for (int i = 0; i < 8; i++)
#pragma unroll
                for (int j = 0; j < 4; j++)
                    fma2(acc[i][j], ap[i], b2[j]);
        }
    }

    // epilogue
    const int c0 = tx * 8;
    float4 bb0 = *(const float4*)(bias + c0);
    float4 bb1 = *(const float4*)(bias + c0 + 4);
    float bb[8] = {bb0.x, bb0.y, bb0.z, bb0.w, bb1.x, bb1.y, bb1.z, bb1.w};
#pragma unroll
    for (int i = 0; i < 8; i++) {
        int r = row0 + ty * 8 + i;
        if (r >= M) continue;
        float v[8];
#pragma unroll
        for (int j = 0; j < 4; j++) {
            float lo, hi;
            unpack2(lo, hi, acc[i][j]);
            float v0 = lo + bb[2 * j];
            float v1 = hi + bb[2 * j + 1];
            if (MODE == 1) {
                v0 = R[(size_t)r * 128 + c0 + 2 * j]     + fmaxf(v0, 0.0f);
                v1 = R[(size_t)r * 128 + c0 + 2 * j + 1] + fmaxf(v1, 0.0f);
            }
            v[2 * j] = v0;
            v[2 * j + 1] = v1;
        }
        *(float4*)(C + (size_t)r * 128 + c0)     = make_float4(v[0], v[1], v[2], v[3]);
        *(float4*)(C + (size_t)r * 128 + c0 + 4) = make_float4(v[4], v[5], v[6], v[7]);
    }
}

__global__ __launch_bounds__(256) void qkv_kernel(
    const float* __restrict__ x,
    const float* __restrict__ Wq, const float* __restrict__ bq,
    const float* __restrict__ Wk, const float* __restrict__ bk,
    const float* __restrict__ Wv, const float* __restrict__ bv, int M)
{
    if (blockIdx.y == 0)      gemm_body<0>(x, Wq, bq, g_Q, nullptr, M);
    else if (blockIdx.y == 1) gemm_body<0>(x, Wk, bk, g_K, nullptr, M);
    else                      gemm_body<0>(x, Wv, bv, g_V, nullptr, M);
}

__global__ __launch_bounds__(256) void out_gemm_kernel(
    const float* __restrict__ Wo, const float* __restrict__ bo,
    float* __restrict__ out, int M)
{
    gemm_body<1>(g_g, Wo, bo, out, g_h, M);
}

// ============================================================
// zero wV / z accumulators
// ============================================================
__global__ void zero_kernel(int n_wv, int n_z)
{
    int i = blockIdx.x * blockDim.x + threadIdx.x;
    int stride = gridDim.x * blockDim.x;
    for (int j = i; j < n_wv; j += stride) g_wV[j] = 0.0f;
    for (int j = i; j < n_z;  j += stride) g_z[j]  = 0.0f;
}

// ============================================================
// edge kernel: one warp per edge.
// ============================================================
__global__ __launch_bounds__(256) void edge_kernel(
    const int* __restrict__ src, const int* __restrict__ dst, int E)
{
    int w = (int)((blockIdx.x * blockDim.x + threadIdx.x) >> 5);
    int lane = threadIdx.x & 31;
    if (w >= E) return;
    int s = src[w];
    int d = dst[w];

    const float4* Q4 = (const float4*)g_Q;
    const float4* K4 = (const float4*)g_K;
    const float4* V4 = (const float4*)g_V;

    float4 q = Q4[(size_t)d * 32 + lane];
    float4 k = K4[(size_t)s * 32 + lane];
    float4 v = V4[(size_t)s * 32 + lane];

    float p = q.x * k.x + q.y * k.y + q.z * k.z + q.w * k.w;
    p += __shfl_xor_sync(0xffffffffu, p, 1);
    p += __shfl_xor_sync(0xffffffffu, p, 2);
    float sc = p * 0.25f;                 // 1/sqrt(16)
    sc = fminf(fmaxf(sc, -5.0f), 5.0f);
    sc = expf(sc);

    if ((lane & 3) == 0) {
        float* zp = &g_z[(size_t)d * NHEADS + (lane >> 2)];
        asm volatile("red.global.add.f32 [%0], %1;" :: "l"(zp), "f"(sc) : "memory");
    }

    float* wp = &g_wV[(size_t)d * 128 + lane * 4];
    asm volatile("red.global.add.v4.f32 [%0], {%1,%2,%3,%4};"
                 :: "l"(wp), "f"(v.x * sc), "f"(v.y * sc), "f"(v.z * sc), "f"(v.w * sc)
                 : "memory");
}

// ============================================================
// attn normalize + residual + LN1 -> h ; LN2(h) -> g
// ============================================================
__global__ __launch_bounds__(256) void attn_ln_kernel(
    const float* __restrict__ x,
    const float* __restrict__ gamma1, const float* __restrict__ beta1,
    const float* __restrict__ gamma2, const float* __restrict__ beta2, int M)
{
    int w = (int)((blockIdx.x * blockDim.x + threadIdx.x) >> 5);
    int lane = threadIdx.x & 31;
    if (w >= M) return;

    const float4* x4  = (const float4*)x;
    const float4* wv4 = (const float4*)g_wV;

    float4 xv = x4[(size_t)w * 32 + lane];
    float4 wv = wv4[(size_t)w * 32 + lane];
    float inv = 1.0f / (g_z[(size_t)w * NHEADS + (lane >> 2)] + 1e-3f);

    float4 y;
    y.x = xv.x + wv.x * inv;
    y.y = xv.y + wv.y * inv;
    y.z = xv.z + wv.z * inv;
    y.w = xv.w + wv.w * inv;

    float s  = y.x + y.y + y.z + y.w;
    float sq = y.x * y.x + y.y * y.y + y.z * y.z + y.w * y.w;
#pragma unroll
    for (int o = 16; o > 0; o >>= 1) {
        s  += __shfl_xor_sync(0xffffffffu, s, o);
        sq += __shfl_xor_sync(0xffffffffu, sq, o);
    }
    float mu   = s * (1.0f / 128.0f);
    float var  = sq * (1.0f / 128.0f) - mu * mu;
    float rstd = rsqrtf(var + 1e-5f);

    float4 g1 = ((const float4*)gamma1)[lane];
    float4 b1 = ((const float4*)beta1)[lane];
    float4 hv;
    hv.x = (y.x - mu) * rstd * g1.x + b1.x;
    hv.y = (y.y - mu) * rstd * g1.y + b1.y;
    hv.z = (y.z - mu) * rstd * g1.z + b1.z;
    hv.w = (y.w - mu) * rstd * g1.w + b1.w;
    ((float4*)g_h)[(size_t)w * 32 + lane] = hv;

    float s2  = hv.x + hv.y + hv.z + hv.w;
    float sq2 = hv.x * hv.x + hv.y * hv.y + hv.z * hv.z + hv.w * hv.w;
#pragma unroll
    for (int o = 16; o > 0; o >>= 1) {
        s2  += __shfl_xor_sync(0xffffffffu, s2, o);
        sq2 += __shfl_xor_sync(0xffffffffu, sq2, o);
    }
    float mu2   = s2 * (1.0f / 128.0f);
    float var2  = sq2 * (1.0f / 128.0f) - mu2 * mu2;
    float rstd2 = rsqrtf(var2 + 1e-5f);

    float4 g2 = ((const float4*)gamma2)[lane];
    float4 b2 = ((const float4*)beta2)[lane];
    float4 gv;
    gv.x = (hv.x - mu2) * rstd2 * g2.x + b2.x;
    gv.y = (hv.y - mu2) * rstd2 * g2.y + b2.y;
    gv.z = (hv.z - mu2) * rstd2 * g2.z + b2.z;
    gv.w = (hv.w - mu2) * rstd2 * g2.w + b2.w;
    ((float4*)g_g)[(size_t)w * 32 + lane] = gv;
}

// ============================================================
extern "C" void kernel_launch(void* const* d_in, const int* in_sizes, int n_in,
                              void* d_out, int out_size)
{
    const float* x      = (const float*)d_in[0];
    const int*   src    = (const int*)  d_in[1];
    const int*   dst    = (const int*)  d_in[2];
    const float* Wq     = (const float*)d_in[3];
    const float* bq     = (const float*)d_in[4];
    const float* Wk     = (const float*)d_in[5];
    const float* bk     = (const float*)d_in[6];
    const float* Wv     = (const float*)d_in[7];
    const float* bv     = (const float*)d_in[8];
    const float* Wo     = (const float*)d_in[9];
    const float* bo     = (const float*)d_in[10];
    const float* gamma1 = (const float*)d_in[11];
    const float* beta1  = (const float*)d_in[12];
    const float* gamma2 = (const float*)d_in[13];
    const float* beta2  = (const float*)d_in[14];
    float* out = (float*)d_out;

    int M = in_sizes[0] / 128;
    int E = in_sizes[1];

    zero_kernel<<<512, 256>>>(M * 128, M * NHEADS);

    dim3 gq((M + 127) / 128, 3);
    qkv_kernel<<<gq, 256>>>(x, Wq, bq, Wk, bk, Wv, bv, M);

    int edge_blocks = (E + 7) / 8;  // 8 warps/block
    edge_kernel<<<edge_blocks, 256>>>(src, dst, E);

    attn_ln_kernel<<<(M * 32 + 255) / 256, 256>>>(x, gamma1, beta1, gamma2, beta2, M);

    out_gemm_kernel<<<(M + 127) / 128, 256>>>(Wo, bo, out, M);
}

// round 6
// speedup vs baseline: 1.5493x; 1.0644x over previous
#include <cuda_runtime.h>
#include <cuda_bf16.h>
#include <mma.h>
#include <math.h>
#include <stdint.h>

using namespace nvcuda;

#define D 128
#define NHEADS 8
#define NMAX 50000

// blocks [0, FSPLIT) use FFMA body; [FSPLIT, nblk) use wmma bf16x3 body
#define FSPLIT 196

// ---- scratch (no allocations allowed; device globals) ----
__device__ float g_Q[NMAX * D];
__device__ float g_K[NMAX * D];
__device__ float g_V[NMAX * D];
__device__ float g_wV[NMAX * D];
__device__ float g_z[NMAX * NHEADS];
__device__ float g_h[NMAX * D];
__device__ float g_g[NMAX * D];

// ============================================================
// shared-memory union layout (static, < 48KB)
//  FFMA:  As 32x129 f32 (16512 B) | Bs 32x128 f32 (16384 B)
//  WMMA:  Ah 128x40 bf16 (10240) | Al (10240) | Bh 32x136 bf16 (8704)
//         | Bl (8704) | stage 8x320 f32 (10240)  = 48128 B
// ============================================================
#define SM_BYTES 48128
#define W_AH 0
#define W_AL 10240
#define W_BH 20480
#define W_BL 29184
#define W_ST 37888
#define AS_LD 40     // bf16 elems (80 B)
#define BS_LD 136    // bf16 elems (272 B)
#define ST_LD 20     // f32 elems (80 B)

// ============================================================
// FFMA body (round-1 proven): 128x128 tile, 8x8 microtile
// ============================================================
template <int MODE>
__device__ __forceinline__ void gemm_ffma(
    char* smbuf,
    const float* __restrict__ A, const float* __restrict__ W,
    const float* __restrict__ bias, float* __restrict__ C,
    const float* __restrict__ R, int M)
{
    float (*As)[129] = reinterpret_cast<float(*)[129]>(smbuf);
    float (*Bs)[128] = reinterpret_cast<float(*)[128]>(smbuf + 16512);

    const int tid  = threadIdx.x;
    const int tx   = tid & 15;
    const int ty   = tid >> 4;
    const int row0 = blockIdx.x * 128;

    float acc[8][8];
#pragma unroll
    for (int i = 0; i < 8; i++)
#pragma unroll
        for (int j = 0; j < 8; j++) acc[i][j] = 0.0f;

    const int arow = tid >> 3;
    const int acol = (tid & 7) << 2;
    const int brow = tid >> 5;
    const int bcol = (tid & 31) << 2;

    for (int kk = 0; kk < 128; kk += 32) {
        __syncthreads();
#pragma unroll
        for (int p = 0; p < 4; p++) {
            int r = row0 + arow + p * 32;
            float4 v = make_float4(0.f, 0.f, 0.f, 0.f);
            if (r < M) v = *(const float4*)(A + (size_t)r * 128 + kk + acol);
            int m = arow + p * 32;
            As[acol + 0][m] = v.x;
            As[acol + 1][m] = v.y;
            As[acol + 2][m] = v.z;
            As[acol + 3][m] = v.w;
        }
#pragma unroll
        for (int p = 0; p < 4; p++) {
            int r = kk + brow + p * 8;
            *(float4*)&Bs[brow + p * 8][bcol] =
                *(const float4*)(W + (size_t)r * 128 + bcol);
        }
        __syncthreads();

#pragma unroll
        for (int k = 0; k < 32; k++) {
            float a[8];
#pragma unroll
            for (int i = 0; i < 8; i++) a[i] = As[k][ty * 8 + i];
            float4 b0 = *(float4*)&Bs[k][tx * 8];
            float4 b1 = *(float4*)&Bs[k][tx * 8 + 4];
            float b[8] = {b0.x, b0.y, b0.z, b0.w, b1.x, b1.y, b1.z, b1.w};
#pragma unroll
            for (int i = 0; i < 8; i++)
#pragma unroll
                for (int j = 0; j < 8; j++)
                    acc[i][j] = fmaf(a[i], b[j], acc[i][j]);
        }
    }

    const int c0 = tx * 8;
    float4 bb0 = *(const float4*)(bias + c0);
    float4 bb1 = *(const float4*)(bias + c0 + 4);
    float bb[8] = {bb0.x, bb0.y, bb0.z, bb0.w, bb1.x, bb1.y, bb1.z, bb1.w};
#pragma unroll
    for (int i = 0; i < 8; i++) {
        int r = row0 + ty * 8 + i;
        if (r >= M) continue;
        float v[8];
#pragma unroll
        for (int j = 0; j < 8; j++) {
            float val = acc[i][j] + bb[j];
            if (MODE == 1)
                val = R[(size_t)r * 128 + c0 + j] + fmaxf(val, 0.0f);
            v[j] = val;
        }
        *(float4*)(C + (size_t)r * 128 + c0)     = make_float4(v[0], v[1], v[2], v[3]);
        *(float4*)(C + (size_t)r * 128 + c0 + 4) = make_float4(v[4], v[5], v[6], v[7]);
    }
}

// ============================================================
// WMMA bf16x3 body: 128x128 tile, 8 warps 2(m)x4(n),
// warp = 64x32 = 4x2 m16n16k16 frags, BK=32.
// ============================================================
template <int MODE>
__device__ __forceinline__ void gemm_wmma(
    char* smbuf,
    const float* __restrict__ A, const float* __restrict__ W,
    const float* __restrict__ bias, float* __restrict__ C,
    const float* __restrict__ R, int M)
{
    __nv_bfloat16* Ah = (__nv_bfloat16*)(smbuf + W_AH);
    __nv_bfloat16* Al = (__nv_bfloat16*)(smbuf + W_AL);
    __nv_bfloat16* Bh = (__nv_bfloat16*)(smbuf + W_BH);
    __nv_bfloat16* Bl = (__nv_bfloat16*)(smbuf + W_BL);

    const int tid    = threadIdx.x;
    const int warp   = tid >> 5;
    const int lane   = tid & 31;
    const int warp_m = warp & 1;
    const int warp_n = warp >> 1;
    const int row0   = blockIdx.x * 128;
    float* stg = (float*)(smbuf + W_ST) + warp * 16 * ST_LD;

    wmma::fragment<wmma::accumulator, 16, 16, 16, float> c[4][2];
#pragma unroll
    for (int im = 0; im < 4; im++)
#pragma unroll
        for (int jn = 0; jn < 2; jn++) wmma::fill_fragment(c[im][jn], 0.0f);

    const int arow = tid >> 1;          // 0..127
    const int acol = (tid & 1) * 16;    // 0 or 16
    const int brow = tid >> 3;          // 0..31
    const int bcol = (tid & 7) * 16;    // 0..112

    for (int kk = 0; kk < 128; kk += 32) {
        __syncthreads();
        // A chunk [128 x 32] -> bf16 hi/lo
        {
            int r = row0 + arow;
            const float* srcp = A + (size_t)r * 128 + kk + acol;
            __nv_bfloat16* dh = Ah + arow * AS_LD + acol;
            __nv_bfloat16* dl = Al + arow * AS_LD + acol;
#pragma unroll
            for (int i = 0; i < 16; i += 4) {
                float4 v = (r < M) ? *(const float4*)(srcp + i)
                                   : make_float4(0.f, 0.f, 0.f, 0.f);
                float vv[4] = {v.x, v.y, v.z, v.w};
#pragma unroll
                for (int u = 0; u < 4; u++) {
                    __nv_bfloat16 h = __float2bfloat16(vv[u]);
                    dh[i + u] = h;
                    dl[i + u] = __float2bfloat16(vv[u] - __bfloat162float(h));
                }
            }
        }
        // W chunk [32 x 128] -> bf16 hi/lo
        {
            const float* srcp = W + (size_t)(kk + brow) * 128 + bcol;
            __nv_bfloat16* dh = Bh + brow * BS_LD + bcol;
            __nv_bfloat16* dl = Bl + brow * BS_LD + bcol;
#pragma unroll
            for (int i = 0; i < 16; i += 4) {
                float4 v = *(const float4*)(srcp + i);
                float vv[4] = {v.x, v.y, v.z, v.w};
#pragma unroll
                for (int u = 0; u < 4; u++) {
                    __nv_bfloat16 h = __float2bfloat16(vv[u]);
                    dh[i + u] = h;
                    dl[i + u] = __float2bfloat16(vv[u] - __bfloat162float(h));
                }
            }
        }
        __syncthreads();

#pragma unroll
        for (int ks = 0; ks < 2; ks++) {
            const int k0 = ks * 16;
            wmma::fragment<wmma::matrix_b, 16, 16, 16, __nv_bfloat16, wmma::row_major> b_hi[2], b_lo[2];
#pragma unroll
            for (int jn = 0; jn < 2; jn++) {
                const int n0 = warp_n * 32 + jn * 16;
                wmma::load_matrix_sync(b_hi[jn], Bh + k0 * BS_LD + n0, BS_LD);
                wmma::load_matrix_sync(b_lo[jn], Bl + k0 * BS_LD + n0, BS_LD);
            }
#pragma unroll
            for (int im = 0; im < 4; im++) {
                const int m0 = warp_m * 64 + im * 16;
                wmma::fragment<wmma::matrix_a, 16, 16, 16, __nv_bfloat16, wmma::row_major> a_hi, a_lo;
                wmma::load_matrix_sync(a_hi, Ah + m0 * AS_LD + k0, AS_LD);
                wmma::load_matrix_sync(a_lo, Al + m0 * AS_LD + k0, AS_LD);
#pragma unroll
                for (int jn = 0; jn < 2; jn++) {
                    wmma::mma_sync(c[im][jn], a_hi, b_hi[jn], c[im][jn]);
                    wmma::mma_sync(c[im][jn], a_hi, b_lo[jn], c[im][jn]);
                    wmma::mma_sync(c[im][jn], a_lo, b_hi[jn], c[im][jn]);
                }
            }
        }
    }

    // epilogue via per-warp staging
    const int r  = lane >> 1;
    const int cc = (lane & 1) * 8;
#pragma unroll
    for (int im = 0; im < 4; im++) {
#pragma unroll
        for (int jn = 0; jn < 2; jn++) {
            wmma::store_matrix_sync(stg, c[im][jn], ST_LD, wmma::mem_row_major);
            __syncwarp();
            const int grow = row0 + warp_m * 64 + im * 16 + r;
            const int gcol = warp_n * 32 + jn * 16 + cc;
            if (grow < M) {
                float v[8];
#pragma unroll
                for (int u = 0; u < 8; u++) {
                    float val = stg[r * ST_LD + cc + u] + bias[gcol + u];
                    if (MODE == 1)
                        val = R[(size_t)grow * 128 + gcol + u] + fmaxf(val, 0.0f);
                    v[u] = val;
                }
                *(float4*)(C + (size_t)grow * 128 + gcol)     = make_float4(v[0], v[1], v[2], v[3]);
                *(float4*)(C + (size_t)grow * 128 + gcol + 4) = make_float4(v[4], v[5], v[6], v[7]);
            }
            __syncwarp();
        }
    }
}

// ============================================================
// hybrid GEMM kernels
// ============================================================
__global__ __launch_bounds__(256) void qkv_kernel(
    const float* __restrict__ x,
    const float* __restrict__ Wq, const float* __restrict__ bq,
    const float* __restrict__ Wk, const float* __restrict__ bk,
    const float* __restrict__ Wv, const float* __restrict__ bv, int M)
{
    __shared__ alignas(16) char smbuf[SM_BYTES];
    const float* W; const float* b; float* C;
    if (blockIdx.y == 0)      { W = Wq; b = bq; C = g_Q; }
    else if (blockIdx.y == 1) { W = Wk; b = bk; C = g_K; }
    else                      { W = Wv; b = bv; C = g_V; }
    if (blockIdx.x < FSPLIT) gemm_ffma<0>(smbuf, x, W, b, C, nullptr, M);
    else                     gemm_wmma<0>(smbuf, x, W, b, C, nullptr, M);
}

__global__ __launch_bounds__(256) void out_gemm_kernel(
    const float* __restrict__ Wo, const float* __restrict__ bo,
    float* __restrict__ out, int M)
{
    __shared__ alignas(16) char smbuf[SM_BYTES];
    if (blockIdx.x < FSPLIT) gemm_ffma<1>(smbuf, g_g, Wo, bo, out, g_h, M);
    else                     gemm_wmma<1>(smbuf, g_g, Wo, bo, out, g_h, M);
}

// ============================================================
// zero wV / z accumulators
// ============================================================
__global__ void zero_kernel(int n_wv, int n_z)
{
    int i = blockIdx.x * blockDim.x + threadIdx.x;
    int stride = gridDim.x * blockDim.x;
    for (int j = i; j < n_wv; j += stride) g_wV[j] = 0.0f;
    for (int j = i; j < n_z;  j += stride) g_z[j]  = 0.0f;
}

// ============================================================
// edge kernel: one warp per edge.
// ============================================================
__global__ __launch_bounds__(256) void edge_kernel(
    const int* __restrict__ src, const int* __restrict__ dst, int E)
{
    int w = (int)((blockIdx.x * blockDim.x + threadIdx.x) >> 5);
    int lane = threadIdx.x & 31;
    if (w >= E) return;
    int s = src[w];
    int d = dst[w];

    const float4* Q4 = (const float4*)g_Q;
    const float4* K4 = (const float4*)g_K;
    const float4* V4 = (const float4*)g_V;

    float4 q = Q4[(size_t)d * 32 + lane];
    float4 k = K4[(size_t)s * 32 + lane];
    float4 v = V4[(size_t)s * 32 + lane];

    float p = q.x * k.x + q.y * k.y + q.z * k.z + q.w * k.w;
    p += __shfl_xor_sync(0xffffffffu, p, 1);
    p += __shfl_xor_sync(0xffffffffu, p, 2);
    float sc = p * 0.25f;                 // 1/sqrt(16)
    sc = fminf(fmaxf(sc, -5.0f), 5.0f);
    sc = expf(sc);

    if ((lane & 3) == 0) {
        float* zp = &g_z[(size_t)d * NHEADS + (lane >> 2)];
        asm volatile("red.global.add.f32 [%0], %1;" :: "l"(zp), "f"(sc) : "memory");
    }

    float* wp = &g_wV[(size_t)d * 128 + lane * 4];
    asm volatile("red.global.add.v4.f32 [%0], {%1,%2,%3,%4};"
                 :: "l"(wp), "f"(v.x * sc), "f"(v.y * sc), "f"(v.z * sc), "f"(v.w * sc)
                 : "memory");
}

// ============================================================
// attn normalize + residual + LN1 -> h ; LN2(h) -> g
// ============================================================
__global__ __launch_bounds__(256) void attn_ln_kernel(
    const float* __restrict__ x,
    const float* __restrict__ gamma1, const float* __restrict__ beta1,
    const float* __restrict__ gamma2, const float* __restrict__ beta2, int M)
{
    int w = (int)((blockIdx.x * blockDim.x + threadIdx.x) >> 5);
    int lane = threadIdx.x & 31;
    if (w >= M) return;

    const float4* x4  = (const float4*)x;
    const float4* wv4 = (const float4*)g_wV;

    float4 xv = x4[(size_t)w * 32 + lane];
    float4 wv = wv4[(size_t)w * 32 + lane];
    float inv = 1.0f / (g_z[(size_t)w * NHEADS + (lane >> 2)] + 1e-3f);

    float4 y;
    y.x = xv.x + wv.x * inv;
    y.y = xv.y + wv.y * inv;
    y.z = xv.z + wv.z * inv;
    y.w = xv.w + wv.w * inv;

    float s  = y.x + y.y + y.z + y.w;
    float sq = y.x * y.x + y.y * y.y + y.z * y.z + y.w * y.w;
#pragma unroll
    for (int o = 16; o > 0; o >>= 1) {
        s  += __shfl_xor_sync(0xffffffffu, s, o);
        sq += __shfl_xor_sync(0xffffffffu, sq, o);
    }
    float mu   = s * (1.0f / 128.0f);
    float var  = sq * (1.0f / 128.0f) - mu * mu;
    float rstd = rsqrtf(var + 1e-5f);

    float4 g1 = ((const float4*)gamma1)[lane];
    float4 b1 = ((const float4*)beta1)[lane];
    float4 hv;
    hv.x = (y.x - mu) * rstd * g1.x + b1.x;
    hv.y = (y.y - mu) * rstd * g1.y + b1.y;
    hv.z = (y.z - mu) * rstd * g1.z + b1.z;
    hv.w = (y.w - mu) * rstd * g1.w + b1.w;
    ((float4*)g_h)[(size_t)w * 32 + lane] = hv;

    float s2  = hv.x + hv.y + hv.z + hv.w;
    float sq2 = hv.x * hv.x + hv.y * hv.y + hv.z * hv.z + hv.w * hv.w;
#pragma unroll
    for (int o = 16; o > 0; o >>= 1) {
        s2  += __shfl_xor_sync(0xffffffffu, s2, o);
        sq2 += __shfl_xor_sync(0xffffffffu, sq2, o);
    }
    float mu2   = s2 * (1.0f / 128.0f);
    float var2  = sq2 * (1.0f / 128.0f) - mu2 * mu2;
    float rstd2 = rsqrtf(var2 + 1e-5f);

    float4 g2 = ((const float4*)gamma2)[lane];
    float4 b2 = ((const float4*)beta2)[lane];
    float4 gv;
    gv.x = (hv.x - mu2) * rstd2 * g2.x + b2.x;
    gv.y = (hv.y - mu2) * rstd2 * g2.y + b2.y;
    gv.z = (hv.z - mu2) * rstd2 * g2.z + b2.z;
    gv.w = (hv.w - mu2) * rstd2 * g2.w + b2.w;
    ((float4*)g_g)[(size_t)w * 32 + lane] = gv;
}

// ============================================================
extern "C" void kernel_launch(void* const* d_in, const int* in_sizes, int n_in,
                              void* d_out, int out_size)
{
    const float* x      = (const float*)d_in[0];
    const int*   src    = (const int*)  d_in[1];
    const int*   dst    = (const int*)  d_in[2];
    const float* Wq     = (const float*)d_in[3];
    const float* bq     = (const float*)d_in[4];
    const float* Wk     = (const float*)d_in[5];
    const float* bk     = (const float*)d_in[6];
    const float* Wv     = (const float*)d_in[7];
    const float* bv     = (const float*)d_in[8];
    const float* Wo     = (const float*)d_in[9];
    const float* bo     = (const float*)d_in[10];
    const float* gamma1 = (const float*)d_in[11];
    const float* beta1  = (const float*)d_in[12];
    const float* gamma2 = (const float*)d_in[13];
    const float* beta2  = (const float*)d_in[14];
    float* out = (float*)d_out;

    int M = in_sizes[0] / 128;
    int E = in_sizes[1];
    int nblk = (M + 127) / 128;

    zero_kernel<<<512, 256>>>(M * 128, M * NHEADS);

    dim3 gq(nblk, 3);
    qkv_kernel<<<gq, 256>>>(x, Wq, bq, Wk, bk, Wv, bv, M);

    int edge_blocks = (E + 7) / 8;  // 8 warps/block
    edge_kernel<<<edge_blocks, 256>>>(src, dst, E);

    attn_ln_kernel<<<(M * 32 + 255) / 256, 256>>>(x, gamma1, beta1, gamma2, beta2, M);

    out_gemm_kernel<<<nblk, 256>>>(Wo, bo, out, M);
}